// round 7
// baseline (speedup 1.0000x reference)
#include <cuda_runtime.h>
#include <cstdint>

#define NF 128          // node feature dim F
#define EFD 7           // edge feature dim
#define NMAX 100000     // node count

// Scratch for h = nfeat @ W.T + b  (51.2 MB)
__device__ float g_h[(size_t)NMAX * NF];

// ===========================================================================
// Kernel A: tf32 mma.sync GEMM (hi/lo split, 3 mmas) + fused epilogue
//   h = nfeat @ W.T + b ; out = relu(h + root)/degs
// CTA: 128 rows x 128 cols, K=128 (two K=64 A-halves in smem).
// Warps: 2(M) x 4(N); warp tile 64x32; atom m16n8k8.
// ===========================================================================

// smem float offsets (uint32 tf32 patterns)
#define S_WH 0                        // W hi  [128][132]
#define S_WL 16896                    // W lo
#define S_AH 33792                    // A hi  [128][68]
#define S_AL 42496                    // A lo
#define GEMM_SMEM_WORDS 51200
#define GEMM_SMEM_BYTES (GEMM_SMEM_WORDS * 4)

__device__ __forceinline__ void tf32_split_u(float x, uint32_t& uh, uint32_t& ul) {
    asm("cvt.rna.tf32.f32 %0, %1;" : "=r"(uh) : "f"(x));
    float lo = x - __uint_as_float(uh);
    asm("cvt.rna.tf32.f32 %0, %1;" : "=r"(ul) : "f"(lo));
}

__device__ __forceinline__ void mma_tf32(float* d, const uint32_t* a, const uint32_t* b) {
    asm volatile(
        "mma.sync.aligned.m16n8k8.row.col.f32.tf32.tf32.f32 "
        "{%0,%1,%2,%3}, {%4,%5,%6,%7}, {%8,%9}, {%0,%1,%2,%3};"
        : "+f"(d[0]), "+f"(d[1]), "+f"(d[2]), "+f"(d[3])
        : "r"(a[0]), "r"(a[1]), "r"(a[2]), "r"(a[3]),
          "r"(b[0]), "r"(b[1]));
}

__global__ void __launch_bounds__(256, 1)
gemm_h_mma(const float* __restrict__ A,      // nfeat [N,128]
           const float* __restrict__ W,      // [128,128]
           const float* __restrict__ bvec,   // [128]
           const float* __restrict__ root,   // [128]
           const float* __restrict__ degs,   // [N]
           float* __restrict__ hout,         // [N,128]
           float* __restrict__ out,          // [N,128]
           int N)
{
    extern __shared__ uint32_t sm[];

    const int tid  = threadIdx.x;
    const int wid  = tid >> 5;
    const int lane = tid & 31;
    const int g    = lane >> 2;       // 0..7
    const int tg   = lane & 3;        // 0..3
    const int m0   = blockIdx.x * 128;

    const int m_base = (wid & 1) * 64;   // warp M offset
    const int n_base = (wid >> 1) * 32;  // warp N offset

    // ---- load W (128x128), split tf32 hi/lo into padded smem ----
#pragma unroll
    for (int it = 0; it < 16; it++) {
        int idx = it * 256 + tid;            // float4 index
        int r = idx >> 5, c4 = (idx & 31) * 4;
        float4 v = *reinterpret_cast<const float4*>(W + (size_t)r * 128 + c4);
        uint32_t h0, l0, h1, l1, h2, l2, h3, l3;
        tf32_split_u(v.x, h0, l0); tf32_split_u(v.y, h1, l1);
        tf32_split_u(v.z, h2, l2); tf32_split_u(v.w, h3, l3);
        uint32_t o = (uint32_t)(r * 132 + c4);
        sm[S_WH + o + 0] = h0; sm[S_WH + o + 1] = h1;
        sm[S_WH + o + 2] = h2; sm[S_WH + o + 3] = h3;
        sm[S_WL + o + 0] = l0; sm[S_WL + o + 1] = l1;
        sm[S_WL + o + 2] = l2; sm[S_WL + o + 3] = l3;
    }

    float acc[4][4][4];
#pragma unroll
    for (int mt = 0; mt < 4; mt++)
#pragma unroll
        for (int nt = 0; nt < 4; nt++)
#pragma unroll
            for (int q = 0; q < 4; q++) acc[mt][nt][q] = 0.f;

    for (int kh = 0; kh < 2; kh++) {
        __syncthreads();     // protect A smem reuse (no-op cost on kh=0)
        // ---- load A half (128 x 64), split hi/lo ----
#pragma unroll
        for (int it = 0; it < 8; it++) {
            int idx = it * 256 + tid;
            int r = idx >> 4, c4 = (idx & 15) * 4;
            int gm = m0 + r;
            float4 v = make_float4(0.f, 0.f, 0.f, 0.f);
            if (gm < N)
                v = *reinterpret_cast<const float4*>(A + (size_t)gm * 128 + kh * 64 + c4);
            uint32_t h0, l0, h1, l1, h2, l2, h3, l3;
            tf32_split_u(v.x, h0, l0); tf32_split_u(v.y, h1, l1);
            tf32_split_u(v.z, h2, l2); tf32_split_u(v.w, h3, l3);
            uint32_t o = (uint32_t)(r * 68 + c4);
            sm[S_AH + o + 0] = h0; sm[S_AH + o + 1] = h1;
            sm[S_AH + o + 2] = h2; sm[S_AH + o + 3] = h3;
            sm[S_AL + o + 0] = l0; sm[S_AL + o + 1] = l1;
            sm[S_AL + o + 2] = l2; sm[S_AL + o + 3] = l3;
        }
        __syncthreads();

#pragma unroll
        for (int ks = 0; ks < 8; ks++) {
            const int kc = ks * 8;            // col within A half
            const int k0 = kh * 64 + kc;      // col within W (full K)

            uint32_t ah[4][4], al[4][4], bh[4][2], bl[4][2];
#pragma unroll
            for (int mt = 0; mt < 4; mt++) {
                uint32_t o = (uint32_t)((m_base + mt * 16 + g) * 68 + kc + tg);
                ah[mt][0] = sm[S_AH + o];
                ah[mt][1] = sm[S_AH + o + 8 * 68];
                ah[mt][2] = sm[S_AH + o + 4];
                ah[mt][3] = sm[S_AH + o + 8 * 68 + 4];
                al[mt][0] = sm[S_AL + o];
                al[mt][1] = sm[S_AL + o + 8 * 68];
                al[mt][2] = sm[S_AL + o + 4];
                al[mt][3] = sm[S_AL + o + 8 * 68 + 4];
            }
#pragma unroll
            for (int nt = 0; nt < 4; nt++) {
                uint32_t o = (uint32_t)((n_base + nt * 8 + g) * 132 + k0 + tg);
                bh[nt][0] = sm[S_WH + o];
                bh[nt][1] = sm[S_WH + o + 4];
                bl[nt][0] = sm[S_WL + o];
                bl[nt][1] = sm[S_WL + o + 4];
            }
#pragma unroll
            for (int mt = 0; mt < 4; mt++)
#pragma unroll
                for (int nt = 0; nt < 4; nt++) {
                    mma_tf32(acc[mt][nt], ah[mt], bh[nt]);
                    mma_tf32(acc[mt][nt], ah[mt], bl[nt]);
                    mma_tf32(acc[mt][nt], al[mt], bh[nt]);
                }
        }
    }

    // ---- epilogue ----
    // acc[mt][nt]: c0 (row g, col 2tg), c1 (row g, col 2tg+1),
    //              c2 (row g+8, col 2tg), c3 (row g+8, col 2tg+1)
#pragma unroll
    for (int nt = 0; nt < 4; nt++) {
        const int c = n_base + nt * 8 + 2 * tg;
        const float b0 = __ldg(bvec + c),     b1 = __ldg(bvec + c + 1);
        const float r0 = __ldg(root + c),     r1 = __ldg(root + c + 1);
#pragma unroll
        for (int mt = 0; mt < 4; mt++) {
            const int ra = m0 + m_base + mt * 16 + g;
            const int rb = ra + 8;
            if (ra < N) {
                float invd = 1.0f / __ldg(degs + ra);
                float h0 = acc[mt][nt][0] + b0;
                float h1 = acc[mt][nt][1] + b1;
                float2 hv = make_float2(h0, h1);
                float2 ov = make_float2(fmaxf(h0 + r0, 0.f) * invd,
                                        fmaxf(h1 + r1, 0.f) * invd);
                *reinterpret_cast<float2*>(hout + (size_t)ra * 128 + c) = hv;
                *reinterpret_cast<float2*>(out  + (size_t)ra * 128 + c) = ov;
            }
            if (rb < N) {
                float invd = 1.0f / __ldg(degs + rb);
                float h0 = acc[mt][nt][2] + b0;
                float h1 = acc[mt][nt][3] + b1;
                float2 hv = make_float2(h0, h1);
                float2 ov = make_float2(fmaxf(h0 + r0, 0.f) * invd,
                                        fmaxf(h1 + r1, 0.f) * invd);
                *reinterpret_cast<float2*>(hout + (size_t)rb * 128 + c) = hv;
                *reinterpret_cast<float2*>(out  + (size_t)rb * 128 + c) = ov;
            }
        }
    }
}

// ===========================================================================
// Kernel B (unchanged, measured 176us): 8 edges per warp per iteration.
// ===========================================================================
__global__ void __launch_bounds__(256)
edge_kernel(const float* __restrict__ efeat,   // [E,7]
            const float* __restrict__ norm,    // [E]
            const int*   __restrict__ src,
            const int*   __restrict__ dst,
            const float* __restrict__ We,      // [128,7]
            const float* __restrict__ be,      // [128]
            const float* __restrict__ h,       // [N,128]
            float* __restrict__ out,           // [N,128]
            int E)
{
    const int lane = threadIdx.x & 31;
    const int j0   = lane * 4;

    float w[4][EFD], bias[4];
#pragma unroll
    for (int j = 0; j < 4; j++) {
        bias[j] = __ldg(be + j0 + j);
#pragma unroll
        for (int k = 0; k < EFD; k++)
            w[j][k] = __ldg(We + (size_t)(j0 + j) * EFD + k);
    }

    const int warp_id = (blockIdx.x * blockDim.x + threadIdx.x) >> 5;
    const int nwarps  = (gridDim.x * blockDim.x) >> 5;
    const int Emain   = E & ~7;

    for (int e0 = warp_id * 8; e0 < Emain; e0 += nwarps * 8) {
        const int4   sa  = __ldcs(reinterpret_cast<const int4*>(src + e0));
        const int4   sb4 = __ldcs(reinterpret_cast<const int4*>(src + e0 + 4));
        const int4   da  = __ldcs(reinterpret_cast<const int4*>(dst + e0));
        const int4   db  = __ldcs(reinterpret_cast<const int4*>(dst + e0 + 4));
        const float4 na  = __ldcs(reinterpret_cast<const float4*>(norm + e0));
        const float4 nb  = __ldcs(reinterpret_cast<const float4*>(norm + e0 + 4));

        const int s[8] = {sa.x, sa.y, sa.z, sa.w, sb4.x, sb4.y, sb4.z, sb4.w};
        const int d[8] = {da.x, da.y, da.z, da.w, db.x, db.y, db.z, db.w};
        const float nr[8] = {na.x, na.y, na.z, na.w, nb.x, nb.y, nb.z, nb.w};

        float4 hv[8];
#pragma unroll
        for (int u = 0; u < 8; u++)
            hv[u] = *reinterpret_cast<const float4*>(h + (size_t)s[u] * NF + j0);

        float ef[56];
#pragma unroll
        for (int q = 0; q < 14; q++)
            *reinterpret_cast<float4*>(&ef[q * 4]) =
                __ldcs(reinterpret_cast<const float4*>(efeat + (size_t)e0 * EFD + q * 4));

#pragma unroll
        for (int u = 0; u < 8; u++) {
            float v0 = bias[0], v1 = bias[1], v2 = bias[2], v3 = bias[3];
#pragma unroll
            for (int k = 0; k < EFD; k++) {
                float x = ef[u * EFD + k];
                v0 = fmaf(w[0][k], x, v0);
                v1 = fmaf(w[1][k], x, v1);
                v2 = fmaf(w[2][k], x, v2);
                v3 = fmaf(w[3][k], x, v3);
            }
            v0 = fmaxf(hv[u].x + v0, 0.f) * nr[u];
            v1 = fmaxf(hv[u].y + v1, 0.f) * nr[u];
            v2 = fmaxf(hv[u].z + v2, 0.f) * nr[u];
            v3 = fmaxf(hv[u].w + v3, 0.f) * nr[u];

            float* p = out + (size_t)d[u] * NF + j0;
            asm volatile("red.global.add.v4.f32 [%0], {%1, %2, %3, %4};"
                         :: "l"(p), "f"(v0), "f"(v1), "f"(v2), "f"(v3)
                         : "memory");
        }
    }

    if (warp_id == 0) {
        for (int e = Emain; e < E; e++) {
            const int   se = __ldg(src + e);
            const int   de = __ldg(dst + e);
            const float nre = __ldg(norm + e);
            float efs[EFD];
#pragma unroll
            for (int k = 0; k < EFD; k++)
                efs[k] = __ldg(efeat + (size_t)e * EFD + k);
            float4 hvv = *reinterpret_cast<const float4*>(h + (size_t)se * NF + j0);
            float v0 = bias[0], v1 = bias[1], v2 = bias[2], v3 = bias[3];
#pragma unroll
            for (int k = 0; k < EFD; k++) {
                v0 = fmaf(w[0][k], efs[k], v0);
                v1 = fmaf(w[1][k], efs[k], v1);
                v2 = fmaf(w[2][k], efs[k], v2);
                v3 = fmaf(w[3][k], efs[k], v3);
            }
            v0 = fmaxf(hvv.x + v0, 0.f) * nre;
            v1 = fmaxf(hvv.y + v1, 0.f) * nre;
            v2 = fmaxf(hvv.z + v2, 0.f) * nre;
            v3 = fmaxf(hvv.w + v3, 0.f) * nre;
            float* p = out + (size_t)de * NF + j0;
            asm volatile("red.global.add.v4.f32 [%0], {%1, %2, %3, %4};"
                         :: "l"(p), "f"(v0), "f"(v1), "f"(v2), "f"(v3)
                         : "memory");
        }
    }
}

// ---------------------------------------------------------------------------
// Launch.  Input order: nfeat, efeat, degs, norm, src, dst, W, b, We, be, root
// ---------------------------------------------------------------------------
extern "C" void kernel_launch(void* const* d_in, const int* in_sizes, int n_in,
                              void* d_out, int out_size)
{
    const float* nfeat = (const float*)d_in[0];
    const float* efeat = (const float*)d_in[1];
    const float* degs  = (const float*)d_in[2];
    const float* norm  = (const float*)d_in[3];
    const int*   src   = (const int*)  d_in[4];
    const int*   dst   = (const int*)  d_in[5];
    const float* W     = (const float*)d_in[6];
    const float* b     = (const float*)d_in[7];
    const float* We    = (const float*)d_in[8];
    const float* be    = (const float*)d_in[9];
    const float* root  = (const float*)d_in[10];
    float* out = (float*)d_out;

    const int N = in_sizes[0] / NF;
    const int E = in_sizes[4];

    float* h;
    cudaGetSymbolAddress((void**)&h, g_h);

    cudaFuncSetAttribute(gemm_h_mma, cudaFuncAttributeMaxDynamicSharedMemorySize,
                         GEMM_SMEM_BYTES);

    int gridA = (N + 127) / 128;
    gemm_h_mma<<<gridA, 256, GEMM_SMEM_BYTES>>>(nfeat, W, b, root, degs, h, out, N);

    int gridB = 1480;
    edge_kernel<<<gridB, 256>>>(efeat, norm, src, dst, We, be, h, out, E);
}